// round 1
// baseline (speedup 1.0000x reference)
#include <cuda_runtime.h>
#include <math.h>

// ---------------------------------------------------------------------------
// ImplicitMap_fExtrator: 12-layer MLP + input-Jacobian propagation.
// Formulation: per point keep a (C x 4) state [x | g0 g1 g2].
// Each layer: Acc = W @ State  (one GEMM, N = 4*16384 = 65536 cols),
// epilogue: z = Acc[:,0]+b ; x' = softplus(100z)/100 ; g' = sigmoid(100z)*Acc[:,1:4]
// Layer 1 seed handled by initializing grad cols of input state to I3 (rows 0..2).
// Final layer (cout=1, no act) is a dot product -> dedicated kernel.
// ---------------------------------------------------------------------------

#define NPTS  16384
#define NCOL  65536            // NPTS * 4
#define MAXC  960

static const int LCIN [12] = {259,515,512,512,576,576,768,768,768,960,960,896};
static const int LCOUT[12] = {515,512,512,576,576,768,768,768,960,960,896,1};

// ping-pong activation state buffers (252 MB each; static device arrays are the
// sanctioned scratch mechanism — no allocations anywhere)
__device__ float g_actA[(size_t)MAXC * NCOL];
__device__ float g_actB[(size_t)MAXC * NCOL];

// ---------------- packed fp32x2 helpers (Blackwell FFMA2) ------------------
__device__ __forceinline__ unsigned long long pk2(float v) {
    unsigned long long r;
    asm("mov.b64 %0, {%1, %2};" : "=l"(r) : "f"(v), "f"(v));
    return r;
}
__device__ __forceinline__ void fma2(unsigned long long& d,
                                     unsigned long long a, unsigned long long b) {
    asm("fma.rn.f32x2 %0, %1, %2, %0;" : "+l"(d) : "l"(a), "l"(b));
}
__device__ __forceinline__ void upk(unsigned long long v, float& lo, float& hi) {
    asm("mov.b64 {%0, %1}, %2;" : "=f"(lo), "=f"(hi) : "l"(v));
}

// ---------------- init: build state0 + write input_con --------------------
// state col layout: col = 4*p + ch  (ch0 = x, ch1..3 = d/dxyz)
__global__ void init_kernel(const float* __restrict__ inp,
                            const float* __restrict__ lat,
                            float* __restrict__ out_con)
{
    int idx = blockIdx.x * blockDim.x + threadIdx.x;   // over NPTS*259
    if (idx >= NPTS * 259) return;
    int p = idx / 259;
    int c = idx - p * 259;
    int b = p >> 13;                                   // p / 8192
    float v = (c < 3) ? inp[p * 3 + c] : lat[b * 256 + (c - 3)];
    out_con[idx] = v;                                  // (B,N,259) row-major == idx
    float4 q;
    q.x = v;
    q.y = (c == 0) ? 1.f : 0.f;
    q.z = (c == 1) ? 1.f : 0.f;
    q.w = (c == 2) ? 1.f : 0.f;
    *(float4*)(g_actA + (size_t)c * NCOL + 4 * (size_t)p) = q;
}

// ---------------- fused layer GEMM: Y = act(W @ X + b) ---------------------
// Tile 128(M) x 128(N=32 points) x 16(K); 256 threads; thread = 8 rows x 8 cols
// (= 2 complete points). fp32x2 packed along row pairs.
__device__ __forceinline__ void store_row(float* __restrict__ Y, int m, int cout,
                                          size_t colbase, const float* __restrict__ bias,
                                          const float v[8])
{
    if (m >= cout) return;
    float bv = bias[m];
    float* yrow = Y + (size_t)m * NCOL + colbase;
    #pragma unroll
    for (int pt = 0; pt < 2; pt++) {
        float z = v[pt * 4] + bv;
        float A = 100.f * z;
        float e = expf(-fabsf(A));
        float sp = (fmaxf(A, 0.f) + log1pf(e)) * 0.01f;       // softplus(100z)/100
        float sg = (A >= 0.f) ? 1.f / (1.f + e) : e / (1.f + e); // sigmoid(100z)
        float4 o;
        o.x = sp;
        o.y = sg * v[pt * 4 + 1];
        o.z = sg * v[pt * 4 + 2];
        o.w = sg * v[pt * 4 + 3];
        *(float4*)(yrow + pt * 4) = o;
    }
}

__global__ void __launch_bounds__(256, 2)
layer_kernel(const float* __restrict__ W, const float* __restrict__ bias,
             int cin, int cout, int flip)
{
    const float* __restrict__ X = flip ? g_actB : g_actA;
    float*       __restrict__ Y = flip ? g_actA : g_actB;

    __shared__ float Ws[16][136];   // [k][m], padded
    __shared__ float Xs[16][128];   // [k][n]

    const int t    = threadIdx.x;
    const int mblk = blockIdx.x * 128;
    const int nblk = blockIdx.y * 128;
    const int tx   = t & 15,  ty = t >> 4;
    const int n0   = tx * 8,  m0 = ty * 8;

    unsigned long long acc[4][8];
    #pragma unroll
    for (int i = 0; i < 4; i++)
        #pragma unroll
        for (int j = 0; j < 8; j++) acc[i][j] = 0ULL;

    const int ktiles = (cin + 15) >> 4;
    const int kw = t & 15;      // k index for W loads
    const int mw = t >> 4;      // base m for W loads

    for (int kt = 0; kt < ktiles; kt++) {
        const int k0 = kt << 4;
        // W tile: Ws[k][m] = W[mblk+m][k0+k]  (coalesced along k)
        {
            int kg = k0 + kw;
            bool kok = kg < cin;
            #pragma unroll
            for (int i = 0; i < 8; i++) {
                int m = mw + i * 16;
                int row = mblk + m;
                float v = 0.f;
                if (kok && row < cout) v = W[(size_t)row * cin + kg];
                Ws[kw][m] = v;
            }
        }
        // X tile: float4 coalesced
        {
            #pragma unroll
            for (int i = 0; i < 2; i++) {
                int idx = t + i * 256;
                int r = idx >> 5;
                int c4 = (idx & 31) << 2;
                float4 v = make_float4(0.f, 0.f, 0.f, 0.f);
                int kg = k0 + r;
                if (kg < cin)
                    v = *(const float4*)(X + (size_t)kg * NCOL + nblk + c4);
                *(float4*)&Xs[r][c4] = v;
            }
        }
        __syncthreads();

        #pragma unroll
        for (int kk = 0; kk < 16; kk++) {
            // row-pairs of W read directly as 64-bit pairs
            unsigned long long w2[4];
            const unsigned long long* wp = (const unsigned long long*)&Ws[kk][m0];
            #pragma unroll
            for (int i = 0; i < 4; i++) w2[i] = wp[i];
            float4 xa = *(const float4*)&Xs[kk][n0];
            float4 xb = *(const float4*)&Xs[kk][n0 + 4];
            unsigned long long xp[8];
            xp[0] = pk2(xa.x); xp[1] = pk2(xa.y); xp[2] = pk2(xa.z); xp[3] = pk2(xa.w);
            xp[4] = pk2(xb.x); xp[5] = pk2(xb.y); xp[6] = pk2(xb.z); xp[7] = pk2(xb.w);
            #pragma unroll
            for (int i = 0; i < 4; i++)
                #pragma unroll
                for (int j = 0; j < 8; j++)
                    fma2(acc[i][j], w2[i], xp[j]);
        }
        __syncthreads();
    }

    // epilogue (unpack lazily to limit register pressure)
    const size_t colbase = (size_t)nblk + n0;
    #pragma unroll
    for (int i = 0; i < 4; i++) {
        float lo[8], hi[8];
        #pragma unroll
        for (int j = 0; j < 8; j++) upk(acc[i][j], lo[j], hi[j]);
        store_row(Y, mblk + m0 + 2 * i,     cout, colbase, bias, lo);
        store_row(Y, mblk + m0 + 2 * i + 1, cout, colbase, bias, hi);
    }
}

// ---------------- layer 12: cout=1, no activation --------------------------
// out layout (concatenated, fp32): z (B,1,N)=16384 | g (B,N,1,3)=49152 | con (B,N,259)
__global__ void final_kernel(const float* __restrict__ W,
                             const float* __restrict__ bias,
                             float* __restrict__ out)
{
    int p = blockIdx.x * blockDim.x + threadIdx.x;
    if (p >= NPTS) return;
    float ax = 0.f, g0 = 0.f, g1 = 0.f, g2 = 0.f;
    const float4* xp = (const float4*)(g_actB + 4 * (size_t)p);
    #pragma unroll 8
    for (int c = 0; c < 896; c++) {
        float w = __ldg(W + c);
        float4 v = xp[(size_t)c * (NCOL / 4)];
        ax = fmaf(w, v.x, ax);
        g0 = fmaf(w, v.y, g0);
        g1 = fmaf(w, v.z, g1);
        g2 = fmaf(w, v.w, g2);
    }
    out[p] = ax + bias[0];
    float* go = out + NPTS + 3 * (size_t)p;
    go[0] = g0; go[1] = g1; go[2] = g2;
}

// ---------------------------------------------------------------------------
extern "C" void kernel_launch(void* const* d_in, const int* in_sizes, int n_in,
                              void* d_out, int out_size)
{
    const float* input  = (const float*)d_in[0];
    const float* latent = (const float*)d_in[1];
    float* out = (float*)d_out;

    // input_con region starts after z (16384) + g (49152)
    float* out_con = out + NPTS + NPTS * 3;

    {
        int tot = NPTS * 259;
        init_kernel<<<(tot + 255) / 256, 256>>>(input, latent, out_con);
    }

    // layers 1..11: fused GEMM + activation, ping-pong A<->B
    for (int l = 0; l < 11; l++) {
        const float* W = (const float*)d_in[2 + 2 * l];
        const float* b = (const float*)d_in[3 + 2 * l];
        int cin = LCIN[l], cout = LCOUT[l];
        dim3 grid((cout + 127) / 128, NCOL / 128);
        layer_kernel<<<grid, 256>>>(W, b, cin, cout, l & 1);
    }

    // layer 12 reads g_actB (layer-11 output), writes z and g into d_out
    final_kernel<<<NPTS / 256, 256>>>((const float*)d_in[24],
                                      (const float*)d_in[25], out);
}

// round 4
// speedup vs baseline: 2.1671x; 2.1671x over previous
#include <cuda_runtime.h>
#include <cuda_bf16.h>
#include <math.h>
#include <stdint.h>

// ===========================================================================
// ImplicitMap_fExtrator — bf16 3-term-split GEMM on the tensor pipe via
// legacy mma.sync.m16n8k16 (compute_103-safe; tcgen05 needs sm_103a PTX target
// which this toolchain does not emit).
// State per point: 4 rows [x | g0 g1 g2], row-major [n][c] (pitch 960) as
// SEPARATE bf16 hi/lo arrays (split fp32). Per layer:
//   D = Whi*Xhi + Whi*Xlo + Wlo*Xhi  (fp32 accum; dropped Wlo*Xlo ~2^-16)
// Epilogue: z = D[x-row]+b; x' = softplus(100z)/100; g' = sigmoid(100z)*D.
// Gate computed on x-lanes only and shuffled to gradient lanes.
// ===========================================================================

#define NPTS   16384
#define NROWS  65536          // 4 * NPTS state rows
#define PITCH  960

__device__ __nv_bfloat16 g_hiA[(size_t)NROWS * PITCH];
__device__ __nv_bfloat16 g_loA[(size_t)NROWS * PITCH];
__device__ __nv_bfloat16 g_hiB[(size_t)NROWS * PITCH];
__device__ __nv_bfloat16 g_loB[(size_t)NROWS * PITCH];
__device__ __nv_bfloat16 g_Whi[5600000];
__device__ __nv_bfloat16 g_Wlo[5600000];

static const int    LCIN [11] = {259,515,512,512,576,576,768,768,768,960,960};
static const int    LCOUT[11] = {515,512,512,576,576,768,768,768,960,960,896};
static const int    LPIT [11] = {264,520,512,512,576,576,768,768,768,960,960};
static const size_t LWOFF[11] = {0,135960,402200,664344,959256,1291032,1733400,
                                 2323224,2913048,3650328,4571928};

// ---- PTX helpers ----------------------------------------------------------
__device__ __forceinline__ uint32_t smem_u32(const void* p) {
    uint32_t a;
    asm("{ .reg .u64 t; cvta.to.shared.u64 t, %1; cvt.u32.u64 %0, t; }"
        : "=r"(a) : "l"(p));
    return a;
}
__device__ __forceinline__ void cpa16(uint32_t dst, const void* src, int sz) {
    asm volatile("cp.async.cg.shared.global [%0], [%1], 16, %2;"
                 :: "r"(dst), "l"(src), "r"(sz));
}
__device__ __forceinline__ void cpa_commit() {
    asm volatile("cp.async.commit_group;" ::: "memory");
}
__device__ __forceinline__ void ldsm4(uint32_t* r, uint32_t a) {
    asm volatile("ldmatrix.sync.aligned.m8n8.x4.shared.b16 {%0,%1,%2,%3}, [%4];"
                 : "=r"(r[0]), "=r"(r[1]), "=r"(r[2]), "=r"(r[3]) : "r"(a));
}
__device__ __forceinline__ void mma_bf16(float* d, const uint32_t* a,
                                         uint32_t b0, uint32_t b1) {
    asm volatile("mma.sync.aligned.m16n8k16.row.col.f32.bf16.bf16.f32 "
                 "{%0,%1,%2,%3}, {%4,%5,%6,%7}, {%8,%9}, {%0,%1,%2,%3};"
                 : "+f"(d[0]), "+f"(d[1]), "+f"(d[2]), "+f"(d[3])
                 : "r"(a[0]), "r"(a[1]), "r"(a[2]), "r"(a[3]),
                   "r"(b0), "r"(b1));
}
__device__ __forceinline__ void split2(float v, __nv_bfloat16& h, __nv_bfloat16& l) {
    h = __float2bfloat16(v);
    l = __float2bfloat16(v - __bfloat162float(h));
}

// ---- W prep: fp32 -> bf16 hi/lo (pitched) ---------------------------------
__global__ void prep_kernel(const float* __restrict__ W, int cin, int pitch,
                            int count, size_t dstoff)
{
    int idx = blockIdx.x * blockDim.x + threadIdx.x;
    if (idx >= count) return;
    int row = idx / cin, col = idx - row * cin;
    __nv_bfloat16 h, l;
    split2(W[idx], h, l);
    size_t d = dstoff + (size_t)row * pitch + col;
    g_Whi[d] = h;
    g_Wlo[d] = l;
}

// ---- init: build state0 + write input_con ---------------------------------
__global__ void init_kernel(const float* __restrict__ inp,
                            const float* __restrict__ lat,
                            float* __restrict__ out_con)
{
    int idx = blockIdx.x * blockDim.x + threadIdx.x;   // NPTS*259
    if (idx >= NPTS * 259) return;
    int p = idx / 259;
    int c = idx - p * 259;
    int b = p >> 13;
    float v = (c < 3) ? inp[p * 3 + c] : lat[b * 256 + (c - 3)];
    out_con[idx] = v;
    size_t r0 = (size_t)(4 * p) * PITCH + c;
    __nv_bfloat16 h, l;
    split2(v, h, l);
    g_hiA[r0] = h; g_loA[r0] = l;
    #pragma unroll
    for (int ch = 1; ch <= 3; ch++) {
        float gv = (c == ch - 1) ? 1.0f : 0.0f;
        size_t r = (size_t)(4 * p + ch) * PITCH + c;
        g_hiA[r] = __float2bfloat16(gv);
        g_loA[r] = __float2bfloat16(0.0f);
    }
}

// ---- fused layer: CTA tile 128(M) x 128(N cout), Kc=32, 3-stage pipeline --
#define STAGES 3
#define AHI 0
#define ALO 8192
#define BHI 16384
#define BLO 24576
#define STG_SZ 32768
#define SMEM_BYTES (STAGES * STG_SZ)
#define SWZ64(o) ((o) ^ (((o) >> 3) & 0x30))

__global__ void __launch_bounds__(256)
layer_kernel(const float* __restrict__ bias, int cin, int cout,
             int wpitch, size_t woff, int flip)
{
    extern __shared__ char smem[];
    __shared__ float bias_s[128];
    const uint32_t sb = smem_u32(smem);
    const int t = threadIdx.x;
    const int lane = t & 31, wid = t >> 5;

    const __nv_bfloat16* __restrict__ Xhi = flip ? g_hiB : g_hiA;
    const __nv_bfloat16* __restrict__ Xlo = flip ? g_loB : g_loA;
    __nv_bfloat16* __restrict__ Yhi = flip ? g_hiA : g_hiB;
    __nv_bfloat16* __restrict__ Ylo = flip ? g_loA : g_loB;
    const __nv_bfloat16* __restrict__ Wh = g_Whi + woff;
    const __nv_bfloat16* __restrict__ Wl = g_Wlo + woff;

    const int cblk = blockIdx.x * 128;   // cout block (fastest: A shared in L2)
    const int nblk = blockIdx.y * 128;   // state-row block

    if (t < 128) {
        int c = cblk + t;
        bias_s[t] = (c < cout) ? __ldg(bias + c) : 0.f;
    }

    const int ktiles = (cin + 31) >> 5;

    auto load_stage = [&](int s, int kt) {
        const uint32_t base = sb + (uint32_t)s * STG_SZ;
        const int k0 = kt << 5;
        #pragma unroll
        for (int i = 0; i < 2; i++) {              // A tiles: 512 granules
            int li = t + (i << 8);
            int r = li >> 2, g = li & 3;
            int kk = k0 + g * 8, rem = cin - kk;
            int sz = rem >= 8 ? 16 : (rem > 0 ? rem * 2 : 0);
            uint32_t o = SWZ64((uint32_t)(r * 64 + g * 16));
            const size_t so = (size_t)(nblk + r) * PITCH + kk;
            cpa16(base + AHI + o, Xhi + so, sz);
            cpa16(base + ALO + o, Xlo + so, sz);
        }
        #pragma unroll
        for (int i = 0; i < 2; i++) {              // B tiles: 512 granules
            int li = t + (i << 8);
            int r = li >> 2, g = li & 3;
            int row = cblk + r;
            int kk = k0 + g * 8, rem = cin - kk;
            int sz = (row < cout) ? (rem >= 8 ? 16 : (rem > 0 ? rem * 2 : 0)) : 0;
            uint32_t o = SWZ64((uint32_t)(r * 64 + g * 16));
            const size_t so = (size_t)row * wpitch + kk;
            cpa16(base + BHI + o, Wh + so, sz);
            cpa16(base + BLO + o, Wl + so, sz);
        }
        cpa_commit();
    };

    // per-thread fragment addressing (64B rows, XOR-swizzled)
    const int wm = wid >> 2, wn = wid & 3;      // warp tile: 64(M) x 32(N)
    const int seg = lane >> 3, i7 = lane & 7;
    uint32_t aR[4], aX[4];
    #pragma unroll
    for (int mi = 0; mi < 4; mi++) {
        int r = wm * 64 + mi * 16 + (seg & 1) * 8 + i7;
        aR[mi] = (uint32_t)(r * 64);
        aX[mi] = (aR[mi] >> 3) & 0x30;
    }
    const uint32_t akd = (uint32_t)((seg >> 1) * 16);   // byte k-offset
    uint32_t bR[2], bX[2];
    #pragma unroll
    for (int np = 0; np < 2; np++) {
        int r = wn * 32 + np * 16 + (seg >> 1) * 8 + i7;
        bR[np] = (uint32_t)(r * 64);
        bX[np] = (bR[np] >> 3) & 0x30;
    }
    const uint32_t bkd = (uint32_t)((seg & 1) * 16);

    float acc[4][4][4];
    #pragma unroll
    for (int mi = 0; mi < 4; mi++)
        #pragma unroll
        for (int ni = 0; ni < 4; ni++)
            #pragma unroll
            for (int r = 0; r < 4; r++) acc[mi][ni][r] = 0.f;

    auto compute = [&](int s) {
        const uint32_t base = sb + (uint32_t)s * STG_SZ;
        #pragma unroll
        for (int st = 0; st < 2; st++) {
            const uint32_t kb = (uint32_t)(st * 32);
            uint32_t Ah[4][4], Bh[2][4];
            #pragma unroll
            for (int mi = 0; mi < 4; mi++)
                ldsm4(Ah[mi], base + AHI + aR[mi] + ((kb + akd) ^ aX[mi]));
            #pragma unroll
            for (int np = 0; np < 2; np++)
                ldsm4(Bh[np], base + BHI + bR[np] + ((kb + bkd) ^ bX[np]));
            #pragma unroll
            for (int mi = 0; mi < 4; mi++)
                #pragma unroll
                for (int ni = 0; ni < 4; ni++)
                    mma_bf16(acc[mi][ni], Ah[mi],
                             Bh[ni >> 1][(ni & 1) * 2], Bh[ni >> 1][(ni & 1) * 2 + 1]);
            uint32_t Al[4][4];
            #pragma unroll
            for (int mi = 0; mi < 4; mi++)
                ldsm4(Al[mi], base + ALO + aR[mi] + ((kb + akd) ^ aX[mi]));
            #pragma unroll
            for (int mi = 0; mi < 4; mi++)
                #pragma unroll
                for (int ni = 0; ni < 4; ni++)
                    mma_bf16(acc[mi][ni], Al[mi],
                             Bh[ni >> 1][(ni & 1) * 2], Bh[ni >> 1][(ni & 1) * 2 + 1]);
            uint32_t Bl[2][4];
            #pragma unroll
            for (int np = 0; np < 2; np++)
                ldsm4(Bl[np], base + BLO + bR[np] + ((kb + bkd) ^ bX[np]));
            #pragma unroll
            for (int mi = 0; mi < 4; mi++)
                #pragma unroll
                for (int ni = 0; ni < 4; ni++)
                    mma_bf16(acc[mi][ni], Ah[mi],
                             Bl[ni >> 1][(ni & 1) * 2], Bl[ni >> 1][(ni & 1) * 2 + 1]);
        }
    };

    // ---- software pipeline (cp.async groups, 1 commit per stage) ----------
    for (int s = 0; s < STAGES - 1; s++) {
        if (s < ktiles) load_stage(s, s); else cpa_commit();
    }
    for (int kt = 0; kt < ktiles; kt++) {
        int nf = kt + STAGES - 1;
        if (nf < ktiles) load_stage(nf % STAGES, nf); else cpa_commit();
        asm volatile("cp.async.wait_group %0;" :: "n"(STAGES - 1) : "memory");
        __syncthreads();
        compute(kt % STAGES);
        __syncthreads();
    }

    // ---- epilogue ----------------------------------------------------------
    const unsigned FULL = 0xffffffffu;
    const int srcl = lane & ~12;           // lane holding the x-row (gate) value
    const bool is_x = (lane & 12) == 0;
    const int q = lane >> 2, c2 = (lane & 3) * 2;
    #pragma unroll
    for (int mi = 0; mi < 4; mi++) {
        int r0 = nblk + wm * 64 + mi * 16 + q;
        __nv_bfloat16* yh0 = Yhi + (size_t)r0 * PITCH;
        __nv_bfloat16* yl0 = Ylo + (size_t)r0 * PITCH;
        __nv_bfloat16* yh1 = yh0 + (size_t)8 * PITCH;
        __nv_bfloat16* yl1 = yl0 + (size_t)8 * PITCH;
        #pragma unroll
        for (int ni = 0; ni < 4; ni++) {
            int nloc = wn * 32 + ni * 8 + c2;
            int cg = cblk + nloc;
            float bv0 = bias_s[nloc], bv1 = bias_s[nloc + 1];
            const float* d = acc[mi][ni];
            #pragma unroll
            for (int rr = 0; rr < 2; rr++) {
                float d0 = d[rr * 2], d1 = d[rr * 2 + 1];
                float z0 = __shfl_sync(FULL, d0, srcl);
                float z1 = __shfl_sync(FULL, d1, srcl);
                float A0 = 100.f * (z0 + bv0);
                float A1 = 100.f * (z1 + bv1);
                float sp0 = 0.f, sg0 = 0.f, sp1 = 0.f, sg1 = 0.f;
                if (is_x) {
                    float e0 = __expf(-fabsf(A0)), e1 = __expf(-fabsf(A1));
                    sp0 = (fmaxf(A0, 0.f) + __logf(1.f + e0)) * 0.01f;
                    sp1 = (fmaxf(A1, 0.f) + __logf(1.f + e1)) * 0.01f;
                    float i0 = __fdividef(1.f, 1.f + e0);
                    float i1 = __fdividef(1.f, 1.f + e1);
                    sg0 = (A0 >= 0.f) ? i0 : e0 * i0;
                    sg1 = (A1 >= 0.f) ? i1 : e1 * i1;
                }
                sg0 = __shfl_sync(FULL, sg0, srcl);
                sg1 = __shfl_sync(FULL, sg1, srcl);
                float y0 = is_x ? sp0 : sg0 * d0;
                float y1 = is_x ? sp1 : sg1 * d1;
                __nv_bfloat16 h0, l0, h1, l1;
                split2(y0, h0, l0);
                split2(y1, h1, l1);
                __nv_bfloat16* yh = rr ? yh1 : yh0;
                __nv_bfloat16* yl = rr ? yl1 : yl0;
                if (cg + 1 < cout) {
                    uint32_t hp = (uint32_t)*(unsigned short*)&h0
                                | ((uint32_t)*(unsigned short*)&h1 << 16);
                    uint32_t lp = (uint32_t)*(unsigned short*)&l0
                                | ((uint32_t)*(unsigned short*)&l1 << 16);
                    *(uint32_t*)(yh + cg) = hp;
                    *(uint32_t*)(yl + cg) = lp;
                } else if (cg < cout) {
                    yh[cg] = h0;
                    yl[cg] = l0;
                }
            }
        }
    }
}

// ---- final layer: cout=1 dot product, warp per state row ------------------
__global__ void final_kernel(const float* __restrict__ W,
                             const float* __restrict__ bias,
                             float* __restrict__ out)
{
    int gw = (blockIdx.x * blockDim.x + threadIdx.x) >> 5;
    int lane = threadIdx.x & 31;
    if (gw >= NROWS) return;
    const __nv_bfloat16* hp = g_hiB + (size_t)gw * PITCH;
    const __nv_bfloat16* lp = g_loB + (size_t)gw * PITCH;
    float s = 0.f;
    for (int i = lane; i < 112; i += 32) {       // 112 * 8 = 896 channels
        uint4 hv = *(const uint4*)(hp + i * 8);
        uint4 lv = *(const uint4*)(lp + i * 8);
        float4 w0 = __ldg((const float4*)W + i * 2);
        float4 w1 = __ldg((const float4*)W + i * 2 + 1);
        const uint32_t* hw = &hv.x;
        const uint32_t* lw = &lv.x;
        float wf2[8] = {w0.x, w0.y, w0.z, w0.w, w1.x, w1.y, w1.z, w1.w};
        #pragma unroll
        for (int qq = 0; qq < 4; qq++) {
            float2 fh = __bfloat1622float2(*(const __nv_bfloat162*)&hw[qq]);
            float2 fl = __bfloat1622float2(*(const __nv_bfloat162*)&lw[qq]);
            s = fmaf(wf2[2 * qq],     fh.x + fl.x, s);
            s = fmaf(wf2[2 * qq + 1], fh.y + fl.y, s);
        }
    }
    #pragma unroll
    for (int o = 16; o; o >>= 1) s += __shfl_xor_sync(0xffffffffu, s, o);
    if (lane == 0) {
        int ch = gw & 3, p = gw >> 2;
        if (ch == 0) out[p] = s + bias[0];
        else         out[NPTS + 3 * (size_t)p + (ch - 1)] = s;
    }
}

// ---------------------------------------------------------------------------
extern "C" void kernel_launch(void* const* d_in, const int* in_sizes, int n_in,
                              void* d_out, int out_size)
{
    const float* input  = (const float*)d_in[0];
    const float* latent = (const float*)d_in[1];
    float* out = (float*)d_out;
    float* out_con = out + NPTS + NPTS * 3;

    for (int l = 0; l < 11; l++) {
        int cnt = LCIN[l] * LCOUT[l];
        prep_kernel<<<(cnt + 255) / 256, 256>>>((const float*)d_in[2 + 2 * l],
                                                LCIN[l], LPIT[l], cnt, LWOFF[l]);
    }
    {
        int tot = NPTS * 259;
        init_kernel<<<(tot + 255) / 256, 256>>>(input, latent, out_con);
    }

    cudaFuncSetAttribute(layer_kernel,
                         cudaFuncAttributeMaxDynamicSharedMemorySize, SMEM_BYTES);

    for (int l = 0; l < 11; l++) {
        const float* b = (const float*)d_in[3 + 2 * l];
        dim3 grid((LCOUT[l] + 127) / 128, NROWS / 128);
        layer_kernel<<<grid, 256, SMEM_BYTES>>>(b, LCIN[l], LCOUT[l],
                                                LPIT[l], LWOFF[l], l & 1);
    }

    final_kernel<<<NROWS * 32 / 256, 256>>>((const float*)d_in[24],
                                            (const float*)d_in[25], out);
}

// round 5
// speedup vs baseline: 2.4356x; 1.1239x over previous
#include <cuda_runtime.h>
#include <cuda_fp16.h>
#include <math.h>
#include <stdint.h>

// ===========================================================================
// ImplicitMap_fExtrator — fp16 3-term-split GEMM on tensor pipe via legacy
// mma.sync.m16n8k16.f16 (compute_103-safe).
// State per point: 4 rows [x | g0 g1 g2], row-major [n][c] (pitch 960) as
// SEPARATE fp16 hi/lo arrays (split fp32). Per layer:
//   D = Whi*Xhi + Whi*Xlo + Wlo*Xhi  (fp32 accum; dropped Wlo*Xlo ~2^-22)
// Epilogue: z = D[x-row]+b; x' = softplus(100z)/100; g' = sigmoid(100z)*D.
// Gate computed on x-lanes only, shuffled to gradient lanes.
// ===========================================================================

#define NPTS   16384
#define NROWS  65536
#define PITCH  960

__device__ __half g_hiA[(size_t)NROWS * PITCH];
__device__ __half g_loA[(size_t)NROWS * PITCH];
__device__ __half g_hiB[(size_t)NROWS * PITCH];
__device__ __half g_loB[(size_t)NROWS * PITCH];
__device__ __half g_Whi[5600000];
__device__ __half g_Wlo[5600000];

static const int    LCIN [11] = {259,515,512,512,576,576,768,768,768,960,960};
static const int    LCOUT[11] = {515,512,512,576,576,768,768,768,960,960,896};
static const int    LPIT [11] = {264,520,512,512,576,576,768,768,768,960,960};
static const size_t LWOFF[11] = {0,135960,402200,664344,959256,1291032,1733400,
                                 2323224,2913048,3650328,4571928};

__device__ const int    d_LCIN [11] = {259,515,512,512,576,576,768,768,768,960,960};
__device__ const int    d_LCOUT[11] = {515,512,512,576,576,768,768,768,960,960,896};
__device__ const int    d_LPIT [11] = {264,520,512,512,576,576,768,768,768,960,960};
__device__ const size_t d_LWOFF[11] = {0,135960,402200,664344,959256,1291032,1733400,
                                       2323224,2913048,3650328,4571928};

// ---- PTX helpers ----------------------------------------------------------
__device__ __forceinline__ uint32_t smem_u32(const void* p) {
    uint32_t a;
    asm("{ .reg .u64 t; cvta.to.shared.u64 t, %1; cvt.u32.u64 %0, t; }"
        : "=r"(a) : "l"(p));
    return a;
}
__device__ __forceinline__ void cpa16(uint32_t dst, const void* src, int sz) {
    asm volatile("cp.async.cg.shared.global [%0], [%1], 16, %2;"
                 :: "r"(dst), "l"(src), "r"(sz));
}
__device__ __forceinline__ void cpa_commit() {
    asm volatile("cp.async.commit_group;" ::: "memory");
}
__device__ __forceinline__ void ldsm4(uint32_t* r, uint32_t a) {
    asm volatile("ldmatrix.sync.aligned.m8n8.x4.shared.b16 {%0,%1,%2,%3}, [%4];"
                 : "=r"(r[0]), "=r"(r[1]), "=r"(r[2]), "=r"(r[3]) : "r"(a));
}
__device__ __forceinline__ void mma_f16(float* d, const uint32_t* a,
                                        uint32_t b0, uint32_t b1) {
    asm volatile("mma.sync.aligned.m16n8k16.row.col.f32.f16.f16.f32 "
                 "{%0,%1,%2,%3}, {%4,%5,%6,%7}, {%8,%9}, {%0,%1,%2,%3};"
                 : "+f"(d[0]), "+f"(d[1]), "+f"(d[2]), "+f"(d[3])
                 : "r"(a[0]), "r"(a[1]), "r"(a[2]), "r"(a[3]),
                   "r"(b0), "r"(b1));
}
__device__ __forceinline__ void split2h(float v, __half& h, __half& l) {
    h = __float2half_rn(v);
    l = __float2half_rn(v - __half2float(h));
}

// ---- fused W prep: all 11 layers in ONE launch ----------------------------
struct WPtrs { const float* w[11]; };

__global__ void prep_all_kernel(WPtrs wp)
{
    int l = blockIdx.y;
    int idx = blockIdx.x * blockDim.x + threadIdx.x;
    int cin = d_LCIN[l];
    int cnt = cin * d_LCOUT[l];
    if (idx >= cnt) return;
    int row = idx / cin, col = idx - row * cin;
    __half h, lo;
    split2h(wp.w[l][idx], h, lo);
    size_t d = d_LWOFF[l] + (size_t)row * d_LPIT[l] + col;
    g_Whi[d] = h;
    g_Wlo[d] = lo;
}

// ---- init: build state0 + write input_con ---------------------------------
__global__ void init_kernel(const float* __restrict__ inp,
                            const float* __restrict__ lat,
                            float* __restrict__ out_con)
{
    int idx = blockIdx.x * blockDim.x + threadIdx.x;   // NPTS*259
    if (idx >= NPTS * 259) return;
    int p = idx / 259;
    int c = idx - p * 259;
    int b = p >> 13;
    float v = (c < 3) ? inp[p * 3 + c] : lat[b * 256 + (c - 3)];
    out_con[idx] = v;
    size_t r0 = (size_t)(4 * p) * PITCH + c;
    __half h, l;
    split2h(v, h, l);
    g_hiA[r0] = h; g_loA[r0] = l;
    #pragma unroll
    for (int ch = 1; ch <= 3; ch++) {
        float gv = (c == ch - 1) ? 1.0f : 0.0f;
        size_t r = (size_t)(4 * p + ch) * PITCH + c;
        g_hiA[r] = __float2half_rn(gv);
        g_loA[r] = __float2half_rn(0.0f);
    }
}

// ---- fused layer: CTA 128(M) x 128(N), Kc=64, 2-stage cp.async pipeline ---
#define AHI 0
#define ALO 16384
#define BHI 32768
#define BLO 49152
#define STG_SZ 65536
#define SMEM_BYTES (2 * STG_SZ)
#define SWZ(o) ((o) ^ (((o) >> 3) & 0x70))

__global__ void __launch_bounds__(256)
layer_kernel(const float* __restrict__ bias, int cin, int cout,
             int wpitch, size_t woff, int flip)
{
    extern __shared__ char smem[];
    __shared__ float bias_s[128];
    const uint32_t sb = smem_u32(smem);
    const int t = threadIdx.x;
    const int lane = t & 31, wid = t >> 5;

    const __half* __restrict__ Xhi = flip ? g_hiB : g_hiA;
    const __half* __restrict__ Xlo = flip ? g_loB : g_loA;
    __half* __restrict__ Yhi = flip ? g_hiA : g_hiB;
    __half* __restrict__ Ylo = flip ? g_loA : g_loB;
    const __half* __restrict__ Wh = g_Whi + woff;
    const __half* __restrict__ Wl = g_Wlo + woff;

    const int cblk = blockIdx.x * 128;
    const int nblk = blockIdx.y * 128;

    if (t < 128) {
        int c = cblk + t;
        bias_s[t] = (c < cout) ? __ldg(bias + c) : 0.f;
    }

    const int ktiles = (cin + 63) >> 6;

    // 4096 granules(16B)/stage, 16 per thread; arr: 0 Ahi,1 Alo,2 Bhi,3 Blo
    auto load_stage = [&](int s, int kt) {
        const uint32_t base = sb + (uint32_t)s * STG_SZ;
        const int k0 = kt << 6;
        #pragma unroll
        for (int i = 0; i < 16; i++) {
            int gi = t + (i << 8);
            int arr = gi >> 10;
            int li = gi & 1023;
            int r = li >> 3, g = li & 7;
            int kk = k0 + g * 8;
            int rem = cin - kk;
            int sz = rem >= 8 ? 16 : (rem > 0 ? rem * 2 : 0);
            uint32_t o = SWZ((uint32_t)(r * 128 + g * 16));
            const void* src;
            uint32_t doff;
            if (arr == 0)      { src = Xhi + (size_t)(nblk + r) * PITCH + kk; doff = AHI; }
            else if (arr == 1) { src = Xlo + (size_t)(nblk + r) * PITCH + kk; doff = ALO; }
            else {
                int row = cblk + r;
                if (row >= cout) sz = 0;
                const __half* W = (arr == 2) ? Wh : Wl;
                src = W + (size_t)row * wpitch + kk;
                doff = (arr == 2) ? BHI : BLO;
            }
            cpa16(base + doff + o, src, sz);
        }
        cpa_commit();
    };

    // fragment addressing (128B rows, SW128)
    const int wm = wid >> 2, wn = wid & 3;       // warp tile 64(M) x 32(N)
    const int seg = lane >> 3, i7 = lane & 7;
    uint32_t aR[4], aX[4];
    #pragma unroll
    for (int mi = 0; mi < 4; mi++) {
        int r = wm * 64 + mi * 16 + (seg & 1) * 8 + i7;
        aR[mi] = (uint32_t)(r * 128);
        aX[mi] = (uint32_t)((r & 7) << 4);
    }
    const uint32_t akd = (uint32_t)((seg >> 1) * 16);
    uint32_t bR[2], bX[2];
    #pragma unroll
    for (int np = 0; np < 2; np++) {
        int r = wn * 32 + np * 16 + (seg >> 1) * 8 + i7;
        bR[np] = (uint32_t)(r * 128);
        bX[np] = (uint32_t)((r & 7) << 4);
    }
    const uint32_t bkd = (uint32_t)((seg & 1) * 16);

    float acc[4][4][4];
    #pragma unroll
    for (int mi = 0; mi < 4; mi++)
        #pragma unroll
        for (int ni = 0; ni < 4; ni++)
            #pragma unroll
            for (int r = 0; r < 4; r++) acc[mi][ni][r] = 0.f;

    auto compute = [&](int s) {
        const uint32_t base = sb + (uint32_t)s * STG_SZ;
        #pragma unroll
        for (int st = 0; st < 4; st++) {
            const uint32_t kb = (uint32_t)(st * 32);
            uint32_t Ah[4][4], Bh[2][4];
            #pragma unroll
            for (int mi = 0; mi < 4; mi++)
                ldsm4(Ah[mi], base + AHI + aR[mi] + ((kb + akd) ^ aX[mi]));
            #pragma unroll
            for (int np = 0; np < 2; np++)
                ldsm4(Bh[np], base + BHI + bR[np] + ((kb + bkd) ^ bX[np]));
            #pragma unroll
            for (int mi = 0; mi < 4; mi++)
                #pragma unroll
                for (int ni = 0; ni < 4; ni++)
                    mma_f16(acc[mi][ni], Ah[mi],
                            Bh[ni >> 1][(ni & 1) * 2], Bh[ni >> 1][(ni & 1) * 2 + 1]);
            uint32_t Al[4][4];
            #pragma unroll
            for (int mi = 0; mi < 4; mi++)
                ldsm4(Al[mi], base + ALO + aR[mi] + ((kb + akd) ^ aX[mi]));
            #pragma unroll
            for (int mi = 0; mi < 4; mi++)
                #pragma unroll
                for (int ni = 0; ni < 4; ni++)
                    mma_f16(acc[mi][ni], Al[mi],
                            Bh[ni >> 1][(ni & 1) * 2], Bh[ni >> 1][(ni & 1) * 2 + 1]);
            uint32_t Bl[2][4];
            #pragma unroll
            for (int np = 0; np < 2; np++)
                ldsm4(Bl[np], base + BLO + bR[np] + ((kb + bkd) ^ bX[np]));
            #pragma unroll
            for (int mi = 0; mi < 4; mi++)
                #pragma unroll
                for (int ni = 0; ni < 4; ni++)
                    mma_f16(acc[mi][ni], Ah[mi],
                            Bl[ni >> 1][(ni & 1) * 2], Bl[ni >> 1][(ni & 1) * 2 + 1]);
        }
    };

    // ---- 2-stage pipeline --------------------------------------------------
    load_stage(0, 0);
    for (int kt = 0; kt < ktiles; kt++) {
        if (kt + 1 < ktiles) {
            load_stage((kt + 1) & 1, kt + 1);
            asm volatile("cp.async.wait_group 1;" ::: "memory");
        } else {
            asm volatile("cp.async.wait_group 0;" ::: "memory");
        }
        __syncthreads();
        compute(kt & 1);
        __syncthreads();
    }

    // ---- epilogue ----------------------------------------------------------
    const unsigned FULL = 0xffffffffu;
    const int srcl = lane & ~12;
    const bool is_x = (lane & 12) == 0;
    const int q = lane >> 2, c2 = (lane & 3) * 2;
    #pragma unroll
    for (int mi = 0; mi < 4; mi++) {
        int r0 = nblk + wm * 64 + mi * 16 + q;
        __half* yh0 = Yhi + (size_t)r0 * PITCH;
        __half* yl0 = Ylo + (size_t)r0 * PITCH;
        __half* yh1 = yh0 + (size_t)8 * PITCH;
        __half* yl1 = yl0 + (size_t)8 * PITCH;
        #pragma unroll
        for (int ni = 0; ni < 4; ni++) {
            int nloc = wn * 32 + ni * 8 + c2;
            int cg = cblk + nloc;
            float bv0 = bias_s[nloc], bv1 = bias_s[nloc + 1];
            const float* d = acc[mi][ni];
            #pragma unroll
            for (int rr = 0; rr < 2; rr++) {
                float d0 = d[rr * 2], d1 = d[rr * 2 + 1];
                float z0 = __shfl_sync(FULL, d0, srcl);
                float z1 = __shfl_sync(FULL, d1, srcl);
                float A0 = 100.f * (z0 + bv0);
                float A1 = 100.f * (z1 + bv1);
                float sp0 = 0.f, sg0 = 0.f, sp1 = 0.f, sg1 = 0.f;
                if (is_x) {
                    float e0 = __expf(-fabsf(A0)), e1 = __expf(-fabsf(A1));
                    sp0 = (fmaxf(A0, 0.f) + __logf(1.f + e0)) * 0.01f;
                    sp1 = (fmaxf(A1, 0.f) + __logf(1.f + e1)) * 0.01f;
                    float i0 = __fdividef(1.f, 1.f + e0);
                    float i1 = __fdividef(1.f, 1.f + e1);
                    sg0 = (A0 >= 0.f) ? i0 : e0 * i0;
                    sg1 = (A1 >= 0.f) ? i1 : e1 * i1;
                }
                sg0 = __shfl_sync(FULL, sg0, srcl);
                sg1 = __shfl_sync(FULL, sg1, srcl);
                float y0 = is_x ? sp0 : sg0 * d0;
                float y1 = is_x ? sp1 : sg1 * d1;
                __half h0, l0, h1, l1;
                split2h(y0, h0, l0);
                split2h(y1, h1, l1);
                __half* yh = rr ? yh1 : yh0;
                __half* yl = rr ? yl1 : yl0;
                if (cg + 1 < cout) {
                    uint32_t hp = (uint32_t)__half_as_ushort(h0)
                                | ((uint32_t)__half_as_ushort(h1) << 16);
                    uint32_t lp = (uint32_t)__half_as_ushort(l0)
                                | ((uint32_t)__half_as_ushort(l1) << 16);
                    *(uint32_t*)(yh + cg) = hp;
                    *(uint32_t*)(yl + cg) = lp;
                } else if (cg < cout) {
                    yh[cg] = h0;
                    yl[cg] = l0;
                }
            }
        }
    }
}

// ---- final layer: cout=1 dot product, warp per state row ------------------
__global__ void final_kernel(const float* __restrict__ W,
                             const float* __restrict__ bias,
                             float* __restrict__ out)
{
    int gw = (blockIdx.x * blockDim.x + threadIdx.x) >> 5;
    int lane = threadIdx.x & 31;
    if (gw >= NROWS) return;
    const __half* hp = g_hiB + (size_t)gw * PITCH;
    const __half* lp = g_loB + (size_t)gw * PITCH;
    float s = 0.f;
    for (int i = lane; i < 112; i += 32) {       // 112 * 8 = 896 channels
        uint4 hv = *(const uint4*)(hp + i * 8);
        uint4 lv = *(const uint4*)(lp + i * 8);
        float4 w0 = __ldg((const float4*)W + i * 2);
        float4 w1 = __ldg((const float4*)W + i * 2 + 1);
        const uint32_t* hw = &hv.x;
        const uint32_t* lw = &lv.x;
        float wf2[8] = {w0.x, w0.y, w0.z, w0.w, w1.x, w1.y, w1.z, w1.w};
        #pragma unroll
        for (int qq = 0; qq < 4; qq++) {
            float2 fh = __half22float2(*(const __half2*)&hw[qq]);
            float2 fl = __half22float2(*(const __half2*)&lw[qq]);
            s = fmaf(wf2[2 * qq],     fh.x + fl.x, s);
            s = fmaf(wf2[2 * qq + 1], fh.y + fl.y, s);
        }
    }
    #pragma unroll
    for (int o = 16; o; o >>= 1) s += __shfl_xor_sync(0xffffffffu, s, o);
    if (lane == 0) {
        int ch = gw & 3, p = gw >> 2;
        if (ch == 0) out[p] = s + bias[0];
        else         out[NPTS + 3 * (size_t)p + (ch - 1)] = s;
    }
}

// ---------------------------------------------------------------------------
extern "C" void kernel_launch(void* const* d_in, const int* in_sizes, int n_in,
                              void* d_out, int out_size)
{
    const float* input  = (const float*)d_in[0];
    const float* latent = (const float*)d_in[1];
    float* out = (float*)d_out;
    float* out_con = out + NPTS + NPTS * 3;

    // single fused prep launch (all 11 weight splits)
    {
        WPtrs wp;
        for (int l = 0; l < 11; l++) wp.w[l] = (const float*)d_in[2 + 2 * l];
        dim3 grid((960 * 960 + 255) / 256, 11);
        prep_all_kernel<<<grid, 256>>>(wp);
    }
    {
        int tot = NPTS * 259;
        init_kernel<<<(tot + 255) / 256, 256>>>(input, latent, out_con);
    }

    cudaFuncSetAttribute(layer_kernel,
                         cudaFuncAttributeMaxDynamicSharedMemorySize, SMEM_BYTES);

    for (int l = 0; l < 11; l++) {
        const float* b = (const float*)d_in[3 + 2 * l];
        dim3 grid((LCOUT[l] + 127) / 128, NROWS / 128);
        layer_kernel<<<grid, 256, SMEM_BYTES>>>(b, LCIN[l], LCOUT[l],
                                                LPIT[l], LWOFF[l], l & 1);
    }

    final_kernel<<<NROWS * 32 / 256, 256>>>((const float*)d_in[24],
                                            (const float*)d_in[25], out);
}

// round 7
// speedup vs baseline: 2.6756x; 1.0985x over previous
#include <cuda_runtime.h>
#include <cuda_fp16.h>
#include <math.h>
#include <stdint.h>

// ===========================================================================
// ImplicitMap_fExtrator — fp16 3-term-split GEMM via mma.sync.m16n8k16.f16.
// Round 6: 2 CTAs/SM (launch_bounds 256,2), Kc=32 x 3 stages (96KB smem),
// single __syncthreads per K-iteration.
// State per point: 4 rows [x | g0 g1 g2], row-major [n][c] (pitch 960) as
// separate fp16 hi/lo arrays. Per layer: D = Whi*Xhi + Wlo*Xhi + Whi*Xlo.
// Epilogue: z = D[x-row]+b; x'=softplus(100z)/100; g'=sigmoid(100z)*D.
// ===========================================================================

#define NPTS   16384
#define NROWS  65536
#define PITCH  960

__device__ __half g_hiA[(size_t)NROWS * PITCH];
__device__ __half g_loA[(size_t)NROWS * PITCH];
__device__ __half g_hiB[(size_t)NROWS * PITCH];
__device__ __half g_loB[(size_t)NROWS * PITCH];
__device__ __half g_Whi[5600000];
__device__ __half g_Wlo[5600000];

static const int    LCIN [11] = {259,515,512,512,576,576,768,768,768,960,960};
static const int    LCOUT[11] = {515,512,512,576,576,768,768,768,960,960,896};
static const int    LPIT [11] = {264,520,512,512,576,576,768,768,768,960,960};
static const size_t LWOFF[11] = {0,135960,402200,664344,959256,1291032,1733400,
                                 2323224,2913048,3650328,4571928};

__device__ const int    d_LCIN [11] = {259,515,512,512,576,576,768,768,768,960,960};
__device__ const int    d_LCOUT[11] = {515,512,512,576,576,768,768,768,960,960,896};
__device__ const int    d_LPIT [11] = {264,520,512,512,576,576,768,768,768,960,960};
__device__ const size_t d_LWOFF[11] = {0,135960,402200,664344,959256,1291032,1733400,
                                       2323224,2913048,3650328,4571928};

// ---- PTX helpers ----------------------------------------------------------
__device__ __forceinline__ uint32_t smem_u32(const void* p) {
    uint32_t a;
    asm("{ .reg .u64 t; cvta.to.shared.u64 t, %1; cvt.u32.u64 %0, t; }"
        : "=r"(a) : "l"(p));
    return a;
}
__device__ __forceinline__ void cpa16(uint32_t dst, const void* src, int sz) {
    asm volatile("cp.async.cg.shared.global [%0], [%1], 16, %2;"
                 :: "r"(dst), "l"(src), "r"(sz));
}
__device__ __forceinline__ void cpa_commit() {
    asm volatile("cp.async.commit_group;" ::: "memory");
}
__device__ __forceinline__ void ldsm4(uint32_t* r, uint32_t a) {
    asm volatile("ldmatrix.sync.aligned.m8n8.x4.shared.b16 {%0,%1,%2,%3}, [%4];"
                 : "=r"(r[0]), "=r"(r[1]), "=r"(r[2]), "=r"(r[3]) : "r"(a));
}
__device__ __forceinline__ void mma_f16(float* d, const uint32_t* a,
                                        uint32_t b0, uint32_t b1) {
    asm volatile("mma.sync.aligned.m16n8k16.row.col.f32.f16.f16.f32 "
                 "{%0,%1,%2,%3}, {%4,%5,%6,%7}, {%8,%9}, {%0,%1,%2,%3};"
                 : "+f"(d[0]), "+f"(d[1]), "+f"(d[2]), "+f"(d[3])
                 : "r"(a[0]), "r"(a[1]), "r"(a[2]), "r"(a[3]),
                   "r"(b0), "r"(b1));
}
__device__ __forceinline__ void split2h(float v, __half& h, __half& l) {
    h = __float2half_rn(v);
    l = __float2half_rn(v - __half2float(h));
}

// ---- fused W prep: all 11 layers in ONE launch ----------------------------
struct WPtrs { const float* w[11]; };

__global__ void prep_all_kernel(WPtrs wp)
{
    int l = blockIdx.y;
    int idx = blockIdx.x * blockDim.x + threadIdx.x;
    int cin = d_LCIN[l];
    int cnt = cin * d_LCOUT[l];
    if (idx >= cnt) return;
    int row = idx / cin, col = idx - row * cin;
    __half h, lo;
    split2h(wp.w[l][idx], h, lo);
    size_t d = d_LWOFF[l] + (size_t)row * d_LPIT[l] + col;
    g_Whi[d] = h;
    g_Wlo[d] = lo;
}

// ---- init: build state0 + write input_con ---------------------------------
__global__ void init_kernel(const float* __restrict__ inp,
                            const float* __restrict__ lat,
                            float* __restrict__ out_con)
{
    int idx = blockIdx.x * blockDim.x + threadIdx.x;   // NPTS*259
    if (idx >= NPTS * 259) return;
    int p = idx / 259;
    int c = idx - p * 259;
    int b = p >> 13;
    float v = (c < 3) ? inp[p * 3 + c] : lat[b * 256 + (c - 3)];
    out_con[idx] = v;
    size_t r0 = (size_t)(4 * p) * PITCH + c;
    __half h, l;
    split2h(v, h, l);
    g_hiA[r0] = h; g_loA[r0] = l;
    #pragma unroll
    for (int ch = 1; ch <= 3; ch++) {
        float gv = (c == ch - 1) ? 1.0f : 0.0f;
        size_t r = (size_t)(4 * p + ch) * PITCH + c;
        g_hiA[r] = __float2half_rn(gv);
        g_loA[r] = __float2half_rn(0.0f);
    }
}

// ---- fused layer: CTA 128(M) x 128(N), Kc=32, 3-stage, 1 sync/iter --------
#define STAGES 3
#define AHI 0
#define ALO 8192
#define BHI 16384
#define BLO 24576
#define STG_SZ 32768
#define SMEM_BYTES (STAGES * STG_SZ)
#define SWZ64(o) ((o) ^ (((o) >> 3) & 0x30))

__global__ void __launch_bounds__(256, 2)
layer_kernel(const float* __restrict__ bias, int cin, int cout,
             int wpitch, size_t woff, int flip)
{
    extern __shared__ char smem[];
    __shared__ float bias_s[128];
    const uint32_t sb = smem_u32(smem);
    const int t = threadIdx.x;
    const int lane = t & 31, wid = t >> 5;

    const __half* __restrict__ Xhi = flip ? g_hiB : g_hiA;
    const __half* __restrict__ Xlo = flip ? g_loB : g_loA;
    __half* __restrict__ Yhi = flip ? g_hiA : g_hiB;
    __half* __restrict__ Ylo = flip ? g_loA : g_loB;
    const __half* __restrict__ Wh = g_Whi + woff;
    const __half* __restrict__ Wl = g_Wlo + woff;

    const int cblk = blockIdx.x * 128;
    const int nblk = blockIdx.y * 128;

    if (t < 128) {
        int c = cblk + t;
        bias_s[t] = (c < cout) ? __ldg(bias + c) : 0.f;
    }

    const int ktiles = (cin + 31) >> 5;

    auto load_stage = [&](int s, int kt) {
        const uint32_t base = sb + (uint32_t)s * STG_SZ;
        const int k0 = kt << 5;
        #pragma unroll
        for (int i = 0; i < 2; i++) {              // A: 512 granules x2 arrays
            int li = t + (i << 8);
            int r = li >> 2, g = li & 3;
            int kk = k0 + g * 8, rem = cin - kk;
            int sz = rem >= 8 ? 16 : (rem > 0 ? rem * 2 : 0);
            uint32_t o = SWZ64((uint32_t)(r * 64 + g * 16));
            const size_t so = (size_t)(nblk + r) * PITCH + kk;
            cpa16(base + AHI + o, Xhi + so, sz);
            cpa16(base + ALO + o, Xlo + so, sz);
        }
        #pragma unroll
        for (int i = 0; i < 2; i++) {              // B: 512 granules x2 arrays
            int li = t + (i << 8);
            int r = li >> 2, g = li & 3;
            int row = cblk + r;
            int kk = k0 + g * 8, rem = cin - kk;
            int sz = (row < cout) ? (rem >= 8 ? 16 : (rem > 0 ? rem * 2 : 0)) : 0;
            uint32_t o = SWZ64((uint32_t)(r * 64 + g * 16));
            const size_t so = (size_t)row * wpitch + kk;
            cpa16(base + BHI + o, Wh + so, sz);
            cpa16(base + BLO + o, Wl + so, sz);
        }
        cpa_commit();
    };

    // fragment addressing (64B rows, XOR-swizzled) — round-4-validated
    const int wm = wid >> 2, wn = wid & 3;       // warp tile 64(M) x 32(N)
    const int seg = lane >> 3, i7 = lane & 7;
    uint32_t aR[4], aX[4];
    #pragma unroll
    for (int mi = 0; mi < 4; mi++) {
        int r = wm * 64 + mi * 16 + (seg & 1) * 8 + i7;
        aR[mi] = (uint32_t)(r * 64);
        aX[mi] = (aR[mi] >> 3) & 0x30;
    }
    const uint32_t akd = (uint32_t)((seg >> 1) * 16);
    uint32_t bR[2], bX[2];
    #pragma unroll
    for (int np = 0; np < 2; np++) {
        int r = wn * 32 + np * 16 + (seg >> 1) * 8 + i7;
        bR[np] = (uint32_t)(r * 64);
        bX[np] = (bR[np] >> 3) & 0x30;
    }
    const uint32_t bkd = (uint32_t)((seg & 1) * 16);

    float acc[4][4][4];
    #pragma unroll
    for (int mi = 0; mi < 4; mi++)
        #pragma unroll
        for (int ni = 0; ni < 4; ni++)
            #pragma unroll
            for (int r = 0; r < 4; r++) acc[mi][ni][r] = 0.f;

    auto compute = [&](int s) {
        const uint32_t base = sb + (uint32_t)s * STG_SZ;
        #pragma unroll
        for (int st = 0; st < 2; st++) {
            const uint32_t kb = (uint32_t)(st * 32);
            uint32_t Ah[4][4], Bh[2][4];
            #pragma unroll
            for (int mi = 0; mi < 4; mi++)
                ldsm4(Ah[mi], base + AHI + aR[mi] + ((kb + akd) ^ aX[mi]));
            #pragma unroll
            for (int np = 0; np < 2; np++)
                ldsm4(Bh[np], base + BHI + bR[np] + ((kb + bkd) ^ bX[np]));
            #pragma unroll
            for (int mi = 0; mi < 4; mi++)
                #pragma unroll
                for (int ni = 0; ni < 4; ni++)
                    mma_f16(acc[mi][ni], Ah[mi],
                            Bh[ni >> 1][(ni & 1) * 2], Bh[ni >> 1][(ni & 1) * 2 + 1]);
            {   // term 2: Al*Bh (Al live only here)
                uint32_t Al[4][4];
                #pragma unroll
                for (int mi = 0; mi < 4; mi++)
                    ldsm4(Al[mi], base + ALO + aR[mi] + ((kb + akd) ^ aX[mi]));
                #pragma unroll
                for (int mi = 0; mi < 4; mi++)
                    #pragma unroll
                    for (int ni = 0; ni < 4; ni++)
                        mma_f16(acc[mi][ni], Al[mi],
                                Bh[ni >> 1][(ni & 1) * 2], Bh[ni >> 1][(ni & 1) * 2 + 1]);
            }
            {   // term 3: Ah*Bl (Bl live only here)
                uint32_t Bl[2][4];
                #pragma unroll
                for (int np = 0; np < 2; np++)
                    ldsm4(Bl[np], base + BLO + bR[np] + ((kb + bkd) ^ bX[np]));
                #pragma unroll
                for (int mi = 0; mi < 4; mi++)
                    #pragma unroll
                    for (int ni = 0; ni < 4; ni++)
                        mma_f16(acc[mi][ni], Ah[mi],
                                Bl[ni >> 1][(ni & 1) * 2], Bl[ni >> 1][(ni & 1) * 2 + 1]);
            }
        }
    };

    // ---- 3-stage pipeline, ONE barrier per iteration -----------------------
    load_stage(0, 0);
    if (ktiles > 1) load_stage(1, 1); else cpa_commit();
    for (int kt = 0; kt < ktiles; kt++) {
        asm volatile("cp.async.wait_group 1;" ::: "memory");
        __syncthreads();
        int nf = kt + 2;
        if (nf < ktiles) load_stage(nf % STAGES, nf); else cpa_commit();
        compute(kt % STAGES);
    }

    // ---- epilogue ----------------------------------------------------------
    const unsigned FULL = 0xffffffffu;
    const int srcl = lane & ~12;
    const bool is_x = (lane & 12) == 0;
    const int q = lane >> 2, c2 = (lane & 3) * 2;
    #pragma unroll
    for (int mi = 0; mi < 4; mi++) {
        int r0 = nblk + wm * 64 + mi * 16 + q;
        __half* yh0 = Yhi + (size_t)r0 * PITCH;
        __half* yl0 = Ylo + (size_t)r0 * PITCH;
        __half* yh1 = yh0 + (size_t)8 * PITCH;
        __half* yl1 = yl0 + (size_t)8 * PITCH;
        #pragma unroll
        for (int ni = 0; ni < 4; ni++) {
            int nloc = wn * 32 + ni * 8 + c2;
            int cg = cblk + nloc;
            float bv0 = bias_s[nloc], bv1 = bias_s[nloc + 1];
            const float* d = acc[mi][ni];
            #pragma unroll
            for (int rr = 0; rr < 2; rr++) {
                float d0 = d[rr * 2], d1 = d[rr * 2 + 1];
                float z0 = __shfl_sync(FULL, d0, srcl);
                float z1 = __shfl_sync(FULL, d1, srcl);
                float A0 = 100.f * (z0 + bv0);
                float A1 = 100.f * (z1 + bv1);
                float sp0 = 0.f, sg0 = 0.f, sp1 = 0.f, sg1 = 0.f;
                if (is_x) {
                    float e0 = __expf(-fabsf(A0)), e1 = __expf(-fabsf(A1));
                    sp0 = (fmaxf(A0, 0.f) + __logf(1.f + e0)) * 0.01f;
                    sp1 = (fmaxf(A1, 0.f) + __logf(1.f + e1)) * 0.01f;
                    float i0 = __fdividef(1.f, 1.f + e0);
                    float i1 = __fdividef(1.f, 1.f + e1);
                    sg0 = (A0 >= 0.f) ? i0 : e0 * i0;
                    sg1 = (A1 >= 0.f) ? i1 : e1 * i1;
                }
                sg0 = __shfl_sync(FULL, sg0, srcl);
                sg1 = __shfl_sync(FULL, sg1, srcl);
                float y0 = is_x ? sp0 : sg0 * d0;
                float y1 = is_x ? sp1 : sg1 * d1;
                __half h0, l0, h1, l1;
                split2h(y0, h0, l0);
                split2h(y1, h1, l1);
                __half* yh = rr ? yh1 : yh0;
                __half* yl = rr ? yl1 : yl0;
                if (cg + 1 < cout) {
                    uint32_t hp = (uint32_t)__half_as_ushort(h0)
                                | ((uint32_t)__half_as_ushort(h1) << 16);
                    uint32_t lp = (uint32_t)__half_as_ushort(l0)
                                | ((uint32_t)__half_as_ushort(l1) << 16);
                    *(uint32_t*)(yh + cg) = hp;
                    *(uint32_t*)(yl + cg) = lp;
                } else if (cg < cout) {
                    yh[cg] = h0;
                    yl[cg] = l0;
                }
            }
        }
    }
}

// ---- final layer: cout=1 dot product, warp per state row ------------------
__global__ void final_kernel(const float* __restrict__ W,
                             const float* __restrict__ bias,
                             float* __restrict__ out)
{
    int gw = (blockIdx.x * blockDim.x + threadIdx.x) >> 5;
    int lane = threadIdx.x & 31;
    if (gw >= NROWS) return;
    const __half* hp = g_hiB + (size_t)gw * PITCH;
    const __half* lp = g_loB + (size_t)gw * PITCH;
    float s = 0.f;
    for (int i = lane; i < 112; i += 32) {       // 112 * 8 = 896 channels
        uint4 hv = *(const uint4*)(hp + i * 8);
        uint4 lv = *(const uint4*)(lp + i * 8);
        float4 w0 = __ldg((const float4*)W + i * 2);
        float4 w1 = __ldg((const float4*)W + i * 2 + 1);
        const uint32_t* hw = &hv.x;
        const uint32_t* lw = &lv.x;
        float wf2[8] = {w0.x, w0.y, w0.z, w0.w, w1.x, w1.y, w1.z, w1.w};
        #pragma unroll
        for (int qq = 0; qq < 4; qq++) {
            float2 fh = __half22float2(*(const __half2*)&hw[qq]);
            float2 fl = __half22float2(*(const __half2*)&lw[qq]);
            s = fmaf(wf2[2 * qq],     fh.x + fl.x, s);
            s = fmaf(wf2[2 * qq + 1], fh.y + fl.y, s);
        }
    }
    #pragma unroll
    for (int o = 16; o; o >>= 1) s += __shfl_xor_sync(0xffffffffu, s, o);
    if (lane == 0) {
        int ch = gw & 3, p = gw >> 2;
        if (ch == 0) out[p] = s + bias[0];
        else         out[NPTS + 3 * (size_t)p + (ch - 1)] = s;
    }
}

// ---------------------------------------------------------------------------
extern "C" void kernel_launch(void* const* d_in, const int* in_sizes, int n_in,
                              void* d_out, int out_size)
{
    const float* input  = (const float*)d_in[0];
    const float* latent = (const float*)d_in[1];
    float* out = (float*)d_out;
    float* out_con = out + NPTS + NPTS * 3;

    {
        WPtrs wp;
        for (int l = 0; l < 11; l++) wp.w[l] = (const float*)d_in[2 + 2 * l];
        dim3 grid((960 * 960 + 255) / 256, 11);
        prep_all_kernel<<<grid, 256>>>(wp);
    }
    {
        int tot = NPTS * 259;
        init_kernel<<<(tot + 255) / 256, 256>>>(input, latent, out_con);
    }

    cudaFuncSetAttribute(layer_kernel,
                         cudaFuncAttributeMaxDynamicSharedMemorySize, SMEM_BYTES);

    for (int l = 0; l < 11; l++) {
        const float* b = (const float*)d_in[3 + 2 * l];
        dim3 grid((LCOUT[l] + 127) / 128, NROWS / 128);
        layer_kernel<<<grid, 256, SMEM_BYTES>>>(b, LCIN[l], LCOUT[l],
                                                LPIT[l], LWOFF[l], l & 1);
    }

    final_kernel<<<NROWS * 32 / 256, 256>>>((const float*)d_in[24],
                                            (const float*)d_in[25], out);
}